// round 16
// baseline (speedup 1.0000x reference)
#include <cuda_runtime.h>
#include <cuda_fp16.h>

#define SEQ    256
#define VOC    96
#define DEND   (SEQ * VOC)           // 24576 dendrites
#define ZROW   DEND                  // masked-position row (code 39)
#define NWARP  16
#define SPB    4                     // samples per block, one merged chain
#define WPOS   (SEQ / NWARP)         // 16 positions per warp per sample

// log_w = log(2*sigmoid(x)), x in (-1,1): range [QLO, QLO+1], width exactly 1.
#define QLO   (-0.62011451f)
#define QS6   (1.0f / 63.0f)         // 6-bit step
#define QZ6   39                     // masked-row code: round(0.620115*63)
#define EPSZ6 (-0.00106705f)         // 39/63 + QLO (masked-row residual)

// 6-bit unsigned quantized transposed table (96B rows): g_q[d*96+v]
__device__ __align__(128) unsigned char g_q[(DEND + 1) * VOC + 128];

// ---------------------------------------------------------------------------
// Kernel A: sigmoid/log + 6-bit quantize + transpose. grid (768,3), block (32,8).
// ---------------------------------------------------------------------------
__global__ void prep_kernel(const float* __restrict__ raw) {
    __shared__ float tile[32][33];      // tile[v_local][d_local]
    const int d0 = blockIdx.x * 32;
    const int v0 = blockIdx.y * 32;
    const int tx = threadIdx.x, ty = threadIdx.y;

    #pragma unroll
    for (int i = ty; i < 32; i += 8) {
        const float x = raw[(v0 + i) * DEND + (d0 + tx)];
        tile[i][tx] = 0.69314718f - __logf(1.0f + __expf(-x));
    }
    __syncthreads();

    const int t  = ty * 32 + tx;        // 0..255
    const int dl = t >> 3;              // d_local 0..31
    const int vq = t & 7;               // which uchar4 of 32 v's

    uchar4 c;
    #pragma unroll
    for (int k = 0; k < 4; k++) {
        const float lw = tile[4 * vq + k][dl];
        int qi = __float2int_rn((lw - QLO) * 63.0f);
        qi = max(0, min(63, qi));
        ((unsigned char*)&c)[k] = (unsigned char)qi;
    }
    *(uchar4*)(g_q + (d0 + dl) * VOC + v0 + 4 * vq) = c;

    if (blockIdx.x == 0 && blockIdx.y == 0 && t < VOC / 4) {
        ((unsigned*)(g_q + ZROW * VOC))[t] = 0x27272727u;   // code 39 per byte
    }
}

// ---------------------------------------------------------------------------
// Kernel B: FOUR samples per block, one merged chain, 512 threads.
// 6-bit codes: FOUR packed rows sum carry-free (bytes <= 252) with 3 IADDs,
// then 4 dp4a extract per QUAD of positions -> ~0.75 instr per vocab entry.
// ---------------------------------------------------------------------------
__global__ void __launch_bounds__(32 * NWARP)
gather_kernel(const int* __restrict__ chars,
              float* __restrict__ out) {
    __shared__ __align__(16) int offs[SPB][SEQ];  // byte offsets of rows
    __shared__ int      cnt[SPB][8];              // per-warp active counts
    __shared__ unsigned part[NWARP][SPB][24][4];  // 24 KB partials

    const int b0   = blockIdx.x * SPB;
    const int t    = threadIdx.x;                 // 0..511
    const int lane = t & 31;
    const int w    = t >> 5;
    const int s0   = w * WPOS;
    const int al   = (lane < 24) ? lane : lane - 8;   // dup lanes share lines
    const int ll4  = al * 4;
    const unsigned char* __restrict__ bp = g_q;

    // Offsets for all 4 samples (1024 chars, 2 per thread).
    #pragma unroll
    for (int r = 0; r < 2; r++) {
        const int i   = t + r * 512;              // 0..1023
        const int smp = i >> 8;
        const int s   = i & (SEQ - 1);
        const int c   = chars[(b0 + smp) * SEQ + s];
        const bool act = (c > 0);
        offs[smp][s] = (act ? (s * VOC + c - 1) : ZROW) * VOC;
        const unsigned m = __ballot_sync(0xffffffffu, act);
        if (lane == 0) cnt[smp][w & 7] = __popc(m);
    }
    __syncthreads();

    unsigned acc[SPB][4];
    #pragma unroll
    for (int s = 0; s < SPB; s++) {
        acc[s][0] = 0u; acc[s][1] = 0u; acc[s][2] = 0u; acc[s][3] = 0u;
    }

    // 4 quad-iterations; per quad x sample: 1 LDS.128 (4 offsets),
    // 4 LDG.32, 3 carry-free IADDs, 4 dp4a.
    #pragma unroll
    for (int g = 0; g < WPOS; g += 4) {
        #pragma unroll
        for (int s = 0; s < SPB; s++) {
            const int4 o = *(const int4*)&offs[s][s0 + g];
            const unsigned xa = *(const unsigned*)(bp + o.x + ll4);
            const unsigned xb = *(const unsigned*)(bp + o.y + ll4);
            const unsigned xc = *(const unsigned*)(bp + o.z + ll4);
            const unsigned xd = *(const unsigned*)(bp + o.w + ll4);
            const unsigned y  = (xa + xb) + (xc + xd);   // bytes <= 252
            acc[s][0] = __dp4a(y, 0x00000001u, acc[s][0]);
            acc[s][1] = __dp4a(y, 0x00000100u, acc[s][1]);
            acc[s][2] = __dp4a(y, 0x00010000u, acc[s][2]);
            acc[s][3] = __dp4a(y, 0x01000000u, acc[s][3]);
        }
    }

    if (lane < 24) {
        #pragma unroll
        for (int s = 0; s < SPB; s++) {
            *(uint4*)&part[w][s][al][0] =
                make_uint4(acc[s][0], acc[s][1], acc[s][2], acc[s][3]);
        }
    }
    __syncthreads();

    // Reduce: 384 threads, thread -> (sample=t/96, vocab=t%96).
    if (t < SPB * VOC) {
        const int smp = t / VOC;
        const int v   = t - smp * VOC;
        unsigned s = 0;
        #pragma unroll
        for (int k = 0; k < NWARP; k++)
            s += part[k][smp][v >> 2][v & 3];
        int nact = 0;
        #pragma unroll
        for (int k = 0; k < 8; k++) nact += cnt[smp][k];
        const float inv  = __frcp_rn((float)max(nact, 1));
        const float corr = 256.0f * QLO - (float)(SEQ - nact) * EPSZ6;
        out[b0 * VOC + t] = __expf((QS6 * (float)s + corr) * inv);
    }
}

// ---------------------------------------------------------------------------
extern "C" void kernel_launch(void* const* d_in, const int* in_sizes, int n_in,
                              void* d_out, int out_size) {
    const int*   chars = (const int*)d_in[0];     // (B, 256) int32
    const float* raw   = (const float*)d_in[1];   // (96, 24576) float32
    float*       out   = (float*)d_out;           // (B, 96) float32

    const int batch = in_sizes[0] / SEQ;

    dim3 pgrid(DEND / 32, VOC / 32);              // (768, 3)
    dim3 pblk(32, 8);
    prep_kernel<<<pgrid, pblk>>>(raw);

    gather_kernel<<<batch / SPB, 32 * NWARP>>>(chars, out);
}

// round 17
// speedup vs baseline: 1.3607x; 1.3607x over previous
#include <cuda_runtime.h>
#include <cuda_fp16.h>

#define SEQ    256
#define VOC    96
#define DEND   (SEQ * VOC)           // 24576 dendrites
#define ZROW   DEND                  // masked-position row (code 39)
#define NWARP  16
#define SPB    4                     // samples per block, one merged chain
#define WPOS   (SEQ / NWARP)         // 16 positions per warp per sample

// log_w = log(2*sigmoid(x)), x in (-1,1): range [QLO, QLO+1], width exactly 1.
#define QLO   (-0.62011451f)
#define QS6   (1.0f / 63.0f)         // 6-bit step
#define EPSZ6 (-0.00106705f)         // 39/63 + QLO (masked-row residual)

// 6-bit unsigned quantized transposed table (96B rows): g_q[d*96+v]
__device__ __align__(128) unsigned char g_q[(DEND + 1) * VOC + 128];

// ---------------------------------------------------------------------------
// Kernel A: sigmoid/log + 6-bit quantize + transpose. grid (768,3), block (32,8).
// ---------------------------------------------------------------------------
__global__ void prep_kernel(const float* __restrict__ raw) {
    __shared__ float tile[32][33];      // tile[v_local][d_local]
    const int d0 = blockIdx.x * 32;
    const int v0 = blockIdx.y * 32;
    const int tx = threadIdx.x, ty = threadIdx.y;

    #pragma unroll
    for (int i = ty; i < 32; i += 8) {
        const float x = raw[(v0 + i) * DEND + (d0 + tx)];
        tile[i][tx] = 0.69314718f - __logf(1.0f + __expf(-x));
    }
    __syncthreads();

    const int t  = ty * 32 + tx;        // 0..255
    const int dl = t >> 3;              // d_local 0..31
    const int vq = t & 7;               // which uchar4 of 32 v's

    uchar4 c;
    #pragma unroll
    for (int k = 0; k < 4; k++) {
        const float lw = tile[4 * vq + k][dl];
        int qi = __float2int_rn((lw - QLO) * 63.0f);
        qi = max(0, min(63, qi));
        ((unsigned char*)&c)[k] = (unsigned char)qi;
    }
    *(uchar4*)(g_q + (d0 + dl) * VOC + v0 + 4 * vq) = c;

    if (blockIdx.x == 0 && blockIdx.y == 0 && t < VOC / 4) {
        ((unsigned*)(g_q + ZROW * VOC))[t] = 0x27272727u;   // code 39 per byte
    }
}

// ---------------------------------------------------------------------------
// Kernel B: FOUR samples per block, one merged chain, 512 threads.
// R13 structure (scalar LDS offsets) + 6-bit QUAD carry-free sums:
// per quad x sample: 4 LDS.32 + 4 LDG.32 + 3 IADD + 4 dp4a.
// ---------------------------------------------------------------------------
__global__ void __launch_bounds__(32 * NWARP)
gather_kernel(const int* __restrict__ chars,
              float* __restrict__ out) {
    __shared__ int      offs[SPB][SEQ];           // byte offsets of rows
    __shared__ int      cnt[SPB][8];              // per-warp active counts
    __shared__ unsigned part[NWARP][SPB][24][4];  // 24 KB partials

    const int b0   = blockIdx.x * SPB;
    const int t    = threadIdx.x;                 // 0..511
    const int lane = t & 31;
    const int w    = t >> 5;
    const int s0   = w * WPOS;
    const int al   = (lane < 24) ? lane : lane - 8;   // dup lanes share lines
    const int ll4  = al * 4;
    const unsigned char* __restrict__ bp = g_q;

    // Offsets for all 4 samples (1024 chars, 2 per thread).
    #pragma unroll
    for (int r = 0; r < 2; r++) {
        const int i   = t + r * 512;              // 0..1023
        const int smp = i >> 8;
        const int s   = i & (SEQ - 1);
        const int c   = chars[(b0 + smp) * SEQ + s];
        const bool act = (c > 0);
        offs[smp][s] = (act ? (s * VOC + c - 1) : ZROW) * VOC;
        const unsigned m = __ballot_sync(0xffffffffu, act);
        if (lane == 0) cnt[smp][w & 7] = __popc(m);
    }
    __syncthreads();

    unsigned acc[SPB][4];
    #pragma unroll
    for (int s = 0; s < SPB; s++) {
        acc[s][0] = 0u; acc[s][1] = 0u; acc[s][2] = 0u; acc[s][3] = 0u;
    }

    // 4 quad-iterations; scalar offset loads (the R14/R16 LDS.128 regression
    // driver removed); 3 carry-free IADDs + 4 dp4a per quad per sample.
    #pragma unroll
    for (int i = 0; i < WPOS; i += 4) {
        #pragma unroll
        for (int s = 0; s < SPB; s++) {
            const int o0 = offs[s][s0 + i];
            const int o1 = offs[s][s0 + i + 1];
            const int o2 = offs[s][s0 + i + 2];
            const int o3 = offs[s][s0 + i + 3];
            const unsigned xa = *(const unsigned*)(bp + o0 + ll4);
            const unsigned xb = *(const unsigned*)(bp + o1 + ll4);
            const unsigned xc = *(const unsigned*)(bp + o2 + ll4);
            const unsigned xd = *(const unsigned*)(bp + o3 + ll4);
            const unsigned y  = (xa + xb) + (xc + xd);   // bytes <= 252
            acc[s][0] = __dp4a(y, 0x00000001u, acc[s][0]);
            acc[s][1] = __dp4a(y, 0x00000100u, acc[s][1]);
            acc[s][2] = __dp4a(y, 0x00010000u, acc[s][2]);
            acc[s][3] = __dp4a(y, 0x01000000u, acc[s][3]);
        }
    }

    if (lane < 24) {
        #pragma unroll
        for (int s = 0; s < SPB; s++) {
            *(uint4*)&part[w][s][al][0] =
                make_uint4(acc[s][0], acc[s][1], acc[s][2], acc[s][3]);
        }
    }
    __syncthreads();

    // Reduce: 384 threads, thread -> (sample=t/96, vocab=t%96).
    if (t < SPB * VOC) {
        const int smp = t / VOC;
        const int v   = t - smp * VOC;
        unsigned s = 0;
        #pragma unroll
        for (int k = 0; k < NWARP; k++)
            s += part[k][smp][v >> 2][v & 3];
        int nact = 0;
        #pragma unroll
        for (int k = 0; k < 8; k++) nact += cnt[smp][k];
        const float inv  = __frcp_rn((float)max(nact, 1));
        const float corr = 256.0f * QLO - (float)(SEQ - nact) * EPSZ6;
        out[b0 * VOC + t] = __expf((QS6 * (float)s + corr) * inv);
    }
}

// ---------------------------------------------------------------------------
extern "C" void kernel_launch(void* const* d_in, const int* in_sizes, int n_in,
                              void* d_out, int out_size) {
    const int*   chars = (const int*)d_in[0];     // (B, 256) int32
    const float* raw   = (const float*)d_in[1];   // (96, 24576) float32
    float*       out   = (float*)d_out;           // (B, 96) float32

    const int batch = in_sizes[0] / SEQ;

    dim3 pgrid(DEND / 32, VOC / 32);              // (768, 3)
    dim3 pblk(32, 8);
    prep_kernel<<<pgrid, pblk>>>(raw);

    gather_kernel<<<batch / SPB, 32 * NWARP>>>(chars, out);
}